// round 6
// baseline (speedup 1.0000x reference)
#include <cuda_runtime.h>
#include <cuda_bf16.h>
#include <math.h>

#define H    2048
#define NH   16
#define NKV  4
#define HD   128
#define S_Q  2048
#define S_E  4096
#define EPS  1e-6f

typedef __nv_bfloat16 bf16;
typedef __nv_bfloat162 bf162;

// ---------------- scratch (split bf16) ----------------
__device__ bf16 g_hsH[S_Q * H],    g_hsL[S_Q * H];
__device__ bf16 g_ehsH[S_E * H],   g_ehsL[S_E * H];
__device__ bf16 g_WqTH[H * H],     g_WqTL[H * H];          // [N=2048][K=2048]
__device__ bf16 g_WkTH[512 * H],   g_WkTL[512 * H];        // [512][2048]
__device__ bf16 g_WvTH[512 * H],   g_WvTL[512 * H];
__device__ bf16 g_WoTH[H * H],     g_WoTL[H * H];
__device__ bf16 g_QH[S_Q * H],     g_QL[S_Q * H];          // normed Q
__device__ bf16 g_KH[S_E * 512],   g_KL[S_E * 512];        // normed K
__device__ bf16 g_VTH[512 * S_E],  g_VTL[512 * S_E];       // V transposed [hd][e]
__device__ bf16 g_AOH[S_Q * H],    g_AOL[S_Q * H];

// ---------------- helpers ----------------
__device__ __forceinline__ unsigned smaddr(const void* p) {
    return (unsigned)__cvta_generic_to_shared(p);
}
__device__ __forceinline__ void ldm_x4(unsigned& r0, unsigned& r1, unsigned& r2, unsigned& r3,
                                       unsigned addr) {
    asm volatile("ldmatrix.sync.aligned.m8n8.x4.shared.b16 {%0,%1,%2,%3},[%4];\n"
                 : "=r"(r0), "=r"(r1), "=r"(r2), "=r"(r3) : "r"(addr));
}
__device__ __forceinline__ void ldm_x2(unsigned& r0, unsigned& r1, unsigned addr) {
    asm volatile("ldmatrix.sync.aligned.m8n8.x2.shared.b16 {%0,%1},[%2];\n"
                 : "=r"(r0), "=r"(r1) : "r"(addr));
}
__device__ __forceinline__ void mma16816(float* c, unsigned a0, unsigned a1, unsigned a2,
                                         unsigned a3, unsigned b0, unsigned b1) {
    asm volatile(
        "mma.sync.aligned.m16n8k16.row.col.f32.bf16.bf16.f32 "
        "{%0,%1,%2,%3},{%4,%5,%6,%7},{%8,%9},{%0,%1,%2,%3};\n"
        : "+f"(c[0]), "+f"(c[1]), "+f"(c[2]), "+f"(c[3])
        : "r"(a0), "r"(a1), "r"(a2), "r"(a3), "r"(b0), "r"(b1));
}
__device__ __forceinline__ void mma3(float* c, const unsigned* ah, const unsigned* al,
                                     unsigned bh0, unsigned bh1, unsigned bl0, unsigned bl1) {
    mma16816(c, ah[0], ah[1], ah[2], ah[3], bh0, bh1);
    mma16816(c, ah[0], ah[1], ah[2], ah[3], bl0, bl1);
    mma16816(c, al[0], al[1], al[2], al[3], bh0, bh1);
}
__device__ __forceinline__ unsigned pack2(float x, float y) {
    bf162 t; t.x = __float2bfloat16(x); t.y = __float2bfloat16(y);
    return *(unsigned*)&t;
}
__device__ __forceinline__ void split2(float x, float y, unsigned& hi, unsigned& lo) {
    bf162 h; h.x = __float2bfloat16(x); h.y = __float2bfloat16(y);
    bf162 l; l.x = __float2bfloat16(x - __bfloat162float(h.x));
    l.y = __float2bfloat16(y - __bfloat162float(h.y));
    hi = *(unsigned*)&h; lo = *(unsigned*)&l;
}

// ---------------- elementwise split fp32 -> (hi, lo) bf16 ----------------
__global__ __launch_bounds__(256) void conv_split(const float* __restrict__ X,
                                                  bf16* __restrict__ Xh, bf16* __restrict__ Xl,
                                                  int n4)
{
    int i = blockIdx.x * 256 + threadIdx.x;
    if (i >= n4) return;
    float4 v = *(const float4*)&X[(size_t)i * 4];
    unsigned h0, l0, h1, l1;
    split2(v.x, v.y, h0, l0);
    split2(v.z, v.w, h1, l1);
    float2 ho, lo;
    ((unsigned*)&ho)[0] = h0; ((unsigned*)&ho)[1] = h1;
    ((unsigned*)&lo)[0] = l0; ((unsigned*)&lo)[1] = l1;
    *(float2*)&Xh[(size_t)i * 4] = ho;
    *(float2*)&Xl[(size_t)i * 4] = lo;
}

// ---------------- transpose + split: W[K][N] -> T[N][K] ----------------
__global__ __launch_bounds__(256) void convT(const float* __restrict__ W,
                                             bf16* __restrict__ Th, bf16* __restrict__ Tl,
                                             int K, int N)
{
    __shared__ float t[32][33];
    const int tx = threadIdx.x & 31;
    const int ty = threadIdx.x >> 5;      // 0..7
    const int n0 = blockIdx.x * 32;
    const int k0 = blockIdx.y * 32;
#pragma unroll
    for (int i = 0; i < 4; i++) {
        int r = ty + 8 * i;
        t[r][tx] = W[(size_t)(k0 + r) * N + n0 + tx];
    }
    __syncthreads();
#pragma unroll
    for (int i = 0; i < 4; i++) {
        int n = ty + 8 * i;
        float v = t[tx][n];
        bf16 h = __float2bfloat16(v);
        Th[(size_t)(n0 + n) * K + k0 + tx] = h;
        Tl[(size_t)(n0 + n) * K + k0 + tx] = __float2bfloat16(v - __bfloat162float(h));
    }
}

// ---------------- GEMM: pure-bf16x3 mainloop, multi-mode epilogue ----------------
// A split [M][K], B split [N][K]. 128x128 tile, k-step 32, 8 warps (2x4), warp 64x32.
// mode 0: fp32 out (optional bias)
// mode 1: bias + per-head(128col) rmsnorm(nw) + split bf16 out [M][N]
// mode 2: bias + split bf16 out TRANSPOSED [N][M] (stride vt_stride = M)
__global__ __launch_bounds__(256) void gemm_x3(
    const bf16* __restrict__ Ahi, const bf16* __restrict__ Alo,
    const bf16* __restrict__ Bhi, const bf16* __restrict__ Blo,
    const float* __restrict__ bias, const float* __restrict__ nw,
    float* __restrict__ Cf, bf16* __restrict__ Chi, bf16* __restrict__ Clo,
    int M, int N, int K, int mode, int vt_stride)
{
    __shared__ unsigned sAhi[128 * 20], sAlo[128 * 20];
    __shared__ unsigned sBhi[128 * 20], sBlo[128 * 20];
    __shared__ float ssq[128];

    const int tid  = threadIdx.x;
    const int lane = tid & 31;
    const int warp = tid >> 5;
    const int wm   = warp >> 2;
    const int wn   = warp & 3;
    const int g    = lane >> 2;
    const int th   = lane & 3;
    const int m0   = blockIdx.y * 128;
    const int n0   = blockIdx.x * 128;

    float acc[4][4][4];
#pragma unroll
    for (int i = 0; i < 4; i++)
#pragma unroll
        for (int j = 0; j < 4; j++)
#pragma unroll
            for (int c = 0; c < 4; c++) acc[i][j][c] = 0.f;

    // prefetch regs: per thread 2 float4 per buffer
    float4 pAh[2], pAl[2], pBh[2], pBl[2];
#pragma unroll
    for (int l = 0; l < 2; l++) {
        int gi = l * 256 + tid;
        int row = gi >> 2, seg = gi & 3;
        pAh[l] = *(const float4*)&Ahi[(size_t)(m0 + row) * K + seg * 8];
        pAl[l] = *(const float4*)&Alo[(size_t)(m0 + row) * K + seg * 8];
        pBh[l] = *(const float4*)&Bhi[(size_t)(n0 + row) * K + seg * 8];
        pBl[l] = *(const float4*)&Blo[(size_t)(n0 + row) * K + seg * 8];
    }

    const int nK = K / 32;
    for (int kt = 0; kt < nK; kt++) {
#pragma unroll
        for (int l = 0; l < 2; l++) {
            int gi = l * 256 + tid;
            int row = gi >> 2, seg = gi & 3;
            int o = row * 20 + seg * 4;
            *(float2*)&sAhi[o]     = make_float2(pAh[l].x, pAh[l].y);
            *(float2*)&sAhi[o + 2] = make_float2(pAh[l].z, pAh[l].w);
            *(float2*)&sAlo[o]     = make_float2(pAl[l].x, pAl[l].y);
            *(float2*)&sAlo[o + 2] = make_float2(pAl[l].z, pAl[l].w);
            *(float2*)&sBhi[o]     = make_float2(pBh[l].x, pBh[l].y);
            *(float2*)&sBhi[o + 2] = make_float2(pBh[l].z, pBh[l].w);
            *(float2*)&sBlo[o]     = make_float2(pBl[l].x, pBl[l].y);
            *(float2*)&sBlo[o + 2] = make_float2(pBl[l].z, pBl[l].w);
        }
        __syncthreads();
        if (kt + 1 < nK) {
            int kk = (kt + 1) * 32;
#pragma unroll
            for (int l = 0; l < 2; l++) {
                int gi = l * 256 + tid;
                int row = gi >> 2, seg = gi & 3;
                pAh[l] = *(const float4*)&Ahi[(size_t)(m0 + row) * K + kk + seg * 8];
                pAl[l] = *(const float4*)&Alo[(size_t)(m0 + row) * K + kk + seg * 8];
                pBh[l] = *(const float4*)&Bhi[(size_t)(n0 + row) * K + kk + seg * 8];
                pBl[l] = *(const float4*)&Blo[(size_t)(n0 + row) * K + kk + seg * 8];
            }
        }
#pragma unroll
        for (int ks = 0; ks < 2; ks++) {
            unsigned ahi[4][4], alo[4][4];
            const int rowl = wm * 64 + (lane & 15);
            const int colu = ks * 8 + (lane >> 4) * 4;
#pragma unroll
            for (int mt = 0; mt < 4; mt++) {
                ldm_x4(ahi[mt][0], ahi[mt][1], ahi[mt][2], ahi[mt][3],
                       smaddr(&sAhi[(rowl + mt * 16) * 20 + colu]));
                ldm_x4(alo[mt][0], alo[mt][1], alo[mt][2], alo[mt][3],
                       smaddr(&sAlo[(rowl + mt * 16) * 20 + colu]));
            }
            const int rowb = lane & 7;
            const int colb = ks * 8 + ((lane >> 3) & 1) * 4;
#pragma unroll
            for (int nt = 0; nt < 4; nt++) {
                unsigned bh0, bh1, bl0, bl1;
                ldm_x2(bh0, bh1, smaddr(&sBhi[(wn * 32 + nt * 8 + rowb) * 20 + colb]));
                ldm_x2(bl0, bl1, smaddr(&sBlo[(wn * 32 + nt * 8 + rowb) * 20 + colb]));
#pragma unroll
                for (int mt = 0; mt < 4; mt++)
                    mma3(acc[mt][nt], ahi[mt], alo[mt], bh0, bh1, bl0, bl1);
            }
        }
        __syncthreads();
    }

    // ---- bias ----
    if (bias) {
#pragma unroll
        for (int nt = 0; nt < 4; nt++) {
            int cc = n0 + wn * 32 + nt * 8 + th * 2;
            float b0 = bias[cc], b1 = bias[cc + 1];
#pragma unroll
            for (int mt = 0; mt < 4; mt++) {
                acc[mt][nt][0] += b0; acc[mt][nt][1] += b1;
                acc[mt][nt][2] += b0; acc[mt][nt][3] += b1;
            }
        }
    }

    if (mode == 0) {
#pragma unroll
        for (int mt = 0; mt < 4; mt++) {
            int r0 = m0 + wm * 64 + mt * 16 + g;
#pragma unroll
            for (int nt = 0; nt < 4; nt++) {
                int cc = n0 + wn * 32 + nt * 8 + th * 2;
                *(float2*)&Cf[(size_t)r0 * N + cc] = make_float2(acc[mt][nt][0], acc[mt][nt][1]);
                *(float2*)&Cf[(size_t)(r0 + 8) * N + cc] = make_float2(acc[mt][nt][2], acc[mt][nt][3]);
            }
        }
    } else if (mode == 1) {
        // per-row sum of squares over this CTA's 128 cols (= one head)
        if (tid < 128) ssq[tid] = 0.f;
        __syncthreads();
#pragma unroll
        for (int mt = 0; mt < 4; mt++) {
            int rl = wm * 64 + mt * 16 + g;
            float p0 = 0.f, p1 = 0.f;
#pragma unroll
            for (int nt = 0; nt < 4; nt++) {
                p0 += acc[mt][nt][0] * acc[mt][nt][0] + acc[mt][nt][1] * acc[mt][nt][1];
                p1 += acc[mt][nt][2] * acc[mt][nt][2] + acc[mt][nt][3] * acc[mt][nt][3];
            }
            atomicAdd(&ssq[rl], p0);
            atomicAdd(&ssq[rl + 8], p1);
        }
        __syncthreads();
#pragma unroll
        for (int mt = 0; mt < 4; mt++) {
            int rl = wm * 64 + mt * 16 + g;
            float inv0 = rsqrtf(ssq[rl] * (1.0f / HD) + EPS);
            float inv1 = rsqrtf(ssq[rl + 8] * (1.0f / HD) + EPS);
#pragma unroll
            for (int nt = 0; nt < 4; nt++) {
                int col = wn * 32 + nt * 8 + th * 2;   // col within head
                float w0 = nw[col], w1 = nw[col + 1];
                unsigned h, l;
                split2(acc[mt][nt][0] * inv0 * w0, acc[mt][nt][1] * inv0 * w1, h, l);
                *(unsigned*)&Chi[(size_t)(m0 + rl) * N + n0 + col] = h;
                *(unsigned*)&Clo[(size_t)(m0 + rl) * N + n0 + col] = l;
                split2(acc[mt][nt][2] * inv1 * w0, acc[mt][nt][3] * inv1 * w1, h, l);
                *(unsigned*)&Chi[(size_t)(m0 + rl + 8) * N + n0 + col] = h;
                *(unsigned*)&Clo[(size_t)(m0 + rl + 8) * N + n0 + col] = l;
            }
        }
    } else {
        // mode 2: transposed split store: T[n][m], stride vt_stride
#pragma unroll
        for (int mt = 0; mt < 4; mt++) {
            int r0 = m0 + wm * 64 + mt * 16 + g;
#pragma unroll
            for (int nt = 0; nt < 4; nt++) {
                int cn = n0 + wn * 32 + nt * 8 + th * 2;
#pragma unroll
                for (int j = 0; j < 2; j++) {
                    float v0 = acc[mt][nt][j];        // row r0
                    float v1 = acc[mt][nt][2 + j];    // row r0+8
                    bf16 h0 = __float2bfloat16(v0);
                    bf16 h1 = __float2bfloat16(v1);
                    Chi[(size_t)(cn + j) * vt_stride + r0] = h0;
                    Chi[(size_t)(cn + j) * vt_stride + r0 + 8] = h1;
                    Clo[(size_t)(cn + j) * vt_stride + r0] =
                        __float2bfloat16(v0 - __bfloat162float(h0));
                    Clo[(size_t)(cn + j) * vt_stride + r0 + 8] =
                        __float2bfloat16(v1 - __bfloat162float(h1));
                }
            }
        }
    }
}

// ---------------- flash attention, pre-split bf16 inputs ----------------
#define FL_SMEM_U32 (2 * (128 * 68) + 2 * (32 * 68) + 2 * (128 * 20))
#define FL_SMEM_BYTES (FL_SMEM_U32 * 4)

__global__ __launch_bounds__(128) void flash_x3b(
    const bf16* __restrict__ Qhi, const bf16* __restrict__ Qlo,
    const bf16* __restrict__ Khi, const bf16* __restrict__ Klo,
    const bf16* __restrict__ VThi, const bf16* __restrict__ VTlo,
    const float* __restrict__ mask,
    bf16* __restrict__ AOhi, bf16* __restrict__ AOlo)
{
    extern __shared__ unsigned smbuf[];
    unsigned* sQhi = smbuf;                    // [128][68]
    unsigned* sQlo = sQhi + 128 * 68;
    unsigned* sKhi = sQlo + 128 * 68;          // [32][68]
    unsigned* sKlo = sKhi + 32 * 68;
    unsigned* sVhi = sKlo + 32 * 68;           // [128][20]  (rows=hd, cols=kv pairs)
    unsigned* sVlo = sVhi + 128 * 20;

    const int h  = blockIdx.y;
    const int kh = h >> 2;
    const int q0 = blockIdx.x * 128;
    const int tid  = threadIdx.x;
    const int lane = tid & 31;
    const int wm   = tid >> 5;
    const int g    = lane >> 2;
    const int th   = lane & 3;

    // Q tile: 128 rows x 128 bf16 (hi+lo)
#pragma unroll
    for (int l = 0; l < 16; l++) {
        int gi = l * 128 + tid;
        int row = gi >> 4, c8 = gi & 15;
        float4 vh = *(const float4*)&Qhi[(size_t)(q0 + row) * (NH * HD) + h * HD + c8 * 8];
        float4 vl = *(const float4*)&Qlo[(size_t)(q0 + row) * (NH * HD) + h * HD + c8 * 8];
        *(float4*)&sQhi[row * 68 + c8 * 4] = vh;
        *(float4*)&sQlo[row * 68 + c8 * 4] = vl;
    }

    const float scale = 0.08838834764831845f;
    float o[2][16][4];
    float m_i[4], l_i[4];
#pragma unroll
    for (int mt = 0; mt < 2; mt++)
#pragma unroll
        for (int nt = 0; nt < 16; nt++)
#pragma unroll
            for (int c = 0; c < 4; c++) o[mt][nt][c] = 0.f;
#pragma unroll
    for (int i = 0; i < 4; i++) { m_i[i] = -INFINITY; l_i[i] = 0.f; }

    for (int e0 = 0; e0 < S_E; e0 += 32) {
        __syncthreads();
        // K tile [32][128] + V tile [128][32] (both hi/lo)
#pragma unroll
        for (int l = 0; l < 4; l++) {
            int gi = l * 128 + tid;
            int krow = gi >> 4, kc8 = gi & 15;
            float4 vh = *(const float4*)&Khi[(size_t)(e0 + krow) * (NKV * HD) + kh * HD + kc8 * 8];
            float4 vl = *(const float4*)&Klo[(size_t)(e0 + krow) * (NKV * HD) + kh * HD + kc8 * 8];
            *(float4*)&sKhi[krow * 68 + kc8 * 4] = vh;
            *(float4*)&sKlo[krow * 68 + kc8 * 4] = vl;

            int vrow = gi >> 2, vc4 = gi & 3;
            float4 wh = *(const float4*)&VThi[(size_t)(kh * HD + vrow) * S_E + e0 + vc4 * 8];
            float4 wl = *(const float4*)&VTlo[(size_t)(kh * HD + vrow) * S_E + e0 + vc4 * 8];
            int ov = vrow * 20 + vc4 * 4;
            *(float2*)&sVhi[ov]     = make_float2(wh.x, wh.y);
            *(float2*)&sVhi[ov + 2] = make_float2(wh.z, wh.w);
            *(float2*)&sVlo[ov]     = make_float2(wl.x, wl.y);
            *(float2*)&sVlo[ov + 2] = make_float2(wl.z, wl.w);
        }
        __syncthreads();

        // S = Q K^T
        float s[2][4][4];
#pragma unroll
        for (int mt = 0; mt < 2; mt++)
#pragma unroll
            for (int nt = 0; nt < 4; nt++)
#pragma unroll
                for (int c = 0; c < 4; c++) s[mt][nt][c] = 0.f;

#pragma unroll
        for (int ks = 0; ks < 8; ks++) {
            unsigned ahi[2][4], alo[2][4];
            const int rowl = wm * 32 + (lane & 15);
            const int colu = ks * 8 + (lane >> 4) * 4;
#pragma unroll
            for (int mt = 0; mt < 2; mt++) {
                ldm_x4(ahi[mt][0], ahi[mt][1], ahi[mt][2], ahi[mt][3],
                       smaddr(&sQhi[(rowl + mt * 16) * 68 + colu]));
                ldm_x4(alo[mt][0], alo[mt][1], alo[mt][2], alo[mt][3],
                       smaddr(&sQlo[(rowl + mt * 16) * 68 + colu]));
            }
            const int rowb = lane & 7;
            const int colb = ks * 8 + ((lane >> 3) & 1) * 4;
#pragma unroll
            for (int nt = 0; nt < 4; nt++) {
                unsigned bh0, bh1, bl0, bl1;
                ldm_x2(bh0, bh1, smaddr(&sKhi[(nt * 8 + rowb) * 68 + colb]));
                ldm_x2(bl0, bl1, smaddr(&sKlo[(nt * 8 + rowb) * 68 + colb]));
#pragma unroll
                for (int mt = 0; mt < 2; mt++)
                    mma3(s[mt][nt], ahi[mt], alo[mt], bh0, bh1, bl0, bl1);
            }
        }

        // online softmax
#pragma unroll
        for (int mt = 0; mt < 2; mt++) {
            const int r0 = q0 + wm * 32 + mt * 16 + g;
#pragma unroll
            for (int nt = 0; nt < 4; nt++) {
                const int cb = e0 + nt * 8 + th * 2;
                float2 mk0 = *(const float2*)&mask[(size_t)r0 * S_E + cb];
                float2 mk1 = *(const float2*)&mask[(size_t)(r0 + 8) * S_E + cb];
                s[mt][nt][0] = s[mt][nt][0] * scale + mk0.x;
                s[mt][nt][1] = s[mt][nt][1] * scale + mk0.y;
                s[mt][nt][2] = s[mt][nt][2] * scale + mk1.x;
                s[mt][nt][3] = s[mt][nt][3] * scale + mk1.y;
            }
            float mx0 = -INFINITY, mx1 = -INFINITY;
#pragma unroll
            for (int nt = 0; nt < 4; nt++) {
                mx0 = fmaxf(mx0, fmaxf(s[mt][nt][0], s[mt][nt][1]));
                mx1 = fmaxf(mx1, fmaxf(s[mt][nt][2], s[mt][nt][3]));
            }
            mx0 = fmaxf(mx0, __shfl_xor_sync(0xffffffffu, mx0, 1));
            mx0 = fmaxf(mx0, __shfl_xor_sync(0xffffffffu, mx0, 2));
            mx1 = fmaxf(mx1, __shfl_xor_sync(0xffffffffu, mx1, 1));
            mx1 = fmaxf(mx1, __shfl_xor_sync(0xffffffffu, mx1, 2));
            float mn0 = fmaxf(m_i[mt * 2 + 0], mx0);
            float mn1 = fmaxf(m_i[mt * 2 + 1], mx1);
            float cr0 = __expf(m_i[mt * 2 + 0] - mn0);
            float cr1 = __expf(m_i[mt * 2 + 1] - mn1);
            m_i[mt * 2 + 0] = mn0;
            m_i[mt * 2 + 1] = mn1;
            float sm0 = 0.f, sm1 = 0.f;
#pragma unroll
            for (int nt = 0; nt < 4; nt++) {
                s[mt][nt][0] = __expf(s[mt][nt][0] - mn0);
                s[mt][nt][1] = __expf(s[mt][nt][1] - mn0);
                s[mt][nt][2] = __expf(s[mt][nt][2] - mn1);
                s[mt][nt][3] = __expf(s[mt][nt][3] - mn1);
                sm0 += s[mt][nt][0] + s[mt][nt][1];
                sm1 += s[mt][nt][2] + s[mt][nt][3];
            }
            sm0 += __shfl_xor_sync(0xffffffffu, sm0, 1);
            sm0 += __shfl_xor_sync(0xffffffffu, sm0, 2);
            sm1 += __shfl_xor_sync(0xffffffffu, sm1, 1);
            sm1 += __shfl_xor_sync(0xffffffffu, sm1, 2);
            l_i[mt * 2 + 0] = l_i[mt * 2 + 0] * cr0 + sm0;
            l_i[mt * 2 + 1] = l_i[mt * 2 + 1] * cr1 + sm1;
#pragma unroll
            for (int nt = 0; nt < 16; nt++) {
                o[mt][nt][0] *= cr0;
                o[mt][nt][1] *= cr0;
                o[mt][nt][2] *= cr1;
                o[mt][nt][3] *= cr1;
            }
        }

        // O += P V
#pragma unroll
        for (int ks2 = 0; ks2 < 2; ks2++) {
            unsigned phi[2][4], plo[2][4];
#pragma unroll
            for (int mt = 0; mt < 2; mt++) {
                const float* sa = s[mt][2 * ks2];
                const float* sb = s[mt][2 * ks2 + 1];
                split2(sa[0], sa[1], phi[mt][0], plo[mt][0]);
                split2(sa[2], sa[3], phi[mt][1], plo[mt][1]);
                split2(sb[0], sb[1], phi[mt][2], plo[mt][2]);
                split2(sb[2], sb[3], phi[mt][3], plo[mt][3]);
            }
            const int rowv = lane & 7;
            const int colv = ks2 * 8 + ((lane >> 3) & 1) * 4;
#pragma unroll
            for (int nt2 = 0; nt2 < 16; nt2++) {
                unsigned vh0, vh1, vl0, vl1;
                ldm_x2(vh0, vh1, smaddr(&sVhi[(nt2 * 8 + rowv) * 20 + colv]));
                ldm_x2(vl0, vl1, smaddr(&sVlo[(nt2 * 8 + rowv) * 20 + colv]));
#pragma unroll
                for (int mt = 0; mt < 2; mt++)
                    mma3(o[mt][nt2], phi[mt], plo[mt], vh0, vh1, vl0, vl1);
            }
        }
    }

    // epilogue: split bf16 store
#pragma unroll
    for (int mt = 0; mt < 2; mt++) {
        const int r0 = q0 + wm * 32 + mt * 16 + g;
        const float inv0 = 1.0f / l_i[mt * 2 + 0];
        const float inv1 = 1.0f / l_i[mt * 2 + 1];
#pragma unroll
        for (int nt2 = 0; nt2 < 16; nt2++) {
            const int cc = h * HD + nt2 * 8 + th * 2;
            unsigned hh, ll;
            split2(o[mt][nt2][0] * inv0, o[mt][nt2][1] * inv0, hh, ll);
            *(unsigned*)&AOhi[(size_t)r0 * (NH * HD) + cc] = hh;
            *(unsigned*)&AOlo[(size_t)r0 * (NH * HD) + cc] = ll;
            split2(o[mt][nt2][2] * inv1, o[mt][nt2][3] * inv1, hh, ll);
            *(unsigned*)&AOhi[(size_t)(r0 + 8) * (NH * HD) + cc] = hh;
            *(unsigned*)&AOlo[(size_t)(r0 + 8) * (NH * HD) + cc] = ll;
        }
    }
}

// ---------------- launch ----------------
#define SYM(p, s) cudaGetSymbolAddress((void**)&p, s)

extern "C" void kernel_launch(void* const* d_in, const int* in_sizes, int n_in,
                              void* d_out, int out_size)
{
    const float* hs   = (const float*)d_in[0];
    const float* ehs  = (const float*)d_in[1];
    const float* mask = (const float*)d_in[2];
    const float* Wq   = (const float*)d_in[3];
    const float* bq   = (const float*)d_in[4];
    const float* Wk   = (const float*)d_in[5];
    const float* bk   = (const float*)d_in[6];
    const float* Wv   = (const float*)d_in[7];
    const float* bv   = (const float*)d_in[8];
    const float* Wo   = (const float*)d_in[9];
    const float* qn   = (const float*)d_in[10];
    const float* kn   = (const float*)d_in[11];
    float* out = (float*)d_out;

    bf16 *hsH, *hsL, *ehsH, *ehsL, *WqTH, *WqTL, *WkTH, *WkTL, *WvTH, *WvTL, *WoTH, *WoTL;
    bf16 *QH, *QL, *KH, *KL, *VTH, *VTL, *AOH, *AOL;
    SYM(hsH, g_hsH);  SYM(hsL, g_hsL);
    SYM(ehsH, g_ehsH); SYM(ehsL, g_ehsL);
    SYM(WqTH, g_WqTH); SYM(WqTL, g_WqTL);
    SYM(WkTH, g_WkTH); SYM(WkTL, g_WkTL);
    SYM(WvTH, g_WvTH); SYM(WvTL, g_WvTL);
    SYM(WoTH, g_WoTH); SYM(WoTL, g_WoTL);
    SYM(QH, g_QH); SYM(QL, g_QL);
    SYM(KH, g_KH); SYM(KL, g_KL);
    SYM(VTH, g_VTH); SYM(VTL, g_VTL);
    SYM(AOH, g_AOH); SYM(AOL, g_AOL);

    cudaFuncSetAttribute(flash_x3b, cudaFuncAttributeMaxDynamicSharedMemorySize, FL_SMEM_BYTES);

    // pre-split activations
    conv_split<<<(S_Q * H / 4 + 255) / 256, 256>>>(hs, hsH, hsL, S_Q * H / 4);
    conv_split<<<(S_E * H / 4 + 255) / 256, 256>>>(ehs, ehsH, ehsL, S_E * H / 4);
    // pre-split + transpose weights -> [N][K]
    convT<<<dim3(H / 32, H / 32), 256>>>(Wq, WqTH, WqTL, H, H);
    convT<<<dim3(512 / 32, H / 32), 256>>>(Wk, WkTH, WkTL, H, 512);
    convT<<<dim3(512 / 32, H / 32), 256>>>(Wv, WvTH, WvTL, H, 512);
    convT<<<dim3(H / 32, H / 32), 256>>>(Wo, WoTH, WoTL, H, H);

    // projections (rmsnorm fused for Q/K; V transposed)
    gemm_x3<<<dim3(H / 128, S_Q / 128), 256>>>(hsH, hsL, WqTH, WqTL, bq, qn,
                                               nullptr, QH, QL, S_Q, H, H, 1, 0);
    gemm_x3<<<dim3(512 / 128, S_E / 128), 256>>>(ehsH, ehsL, WkTH, WkTL, bk, kn,
                                                 nullptr, KH, KL, S_E, 512, H, 1, 0);
    gemm_x3<<<dim3(512 / 128, S_E / 128), 256>>>(ehsH, ehsL, WvTH, WvTL, bv, nullptr,
                                                 nullptr, VTH, VTL, S_E, 512, H, 2, S_E);

    // attention
    flash_x3b<<<dim3(S_Q / 128, NH), 128, FL_SMEM_BYTES>>>(QH, QL, KH, KL, VTH, VTL,
                                                           mask, AOH, AOL);

    // output projection (fp32 out, no bias)
    gemm_x3<<<dim3(H / 128, S_Q / 128), 256>>>(AOH, AOL, WoTH, WoTL, nullptr, nullptr,
                                               out, nullptr, nullptr, S_Q, H, NH * HD, 0, 0);
}

// round 10
// speedup vs baseline: 1.0080x; 1.0080x over previous
#include <cuda_runtime.h>
#include <cuda_bf16.h>
#include <stdint.h>
#include <math.h>

#define H    2048
#define NH   16
#define NKV  4
#define HD   128
#define S_Q  2048
#define S_E  4096
#define EPS  1e-6f

typedef __nv_bfloat16 bf16;
typedef __nv_bfloat162 bf162;

// ---------------- scratch ----------------
__device__ bf16 g_hsH[S_Q * H],    g_hsL[S_Q * H];
__device__ bf16 g_ehsH[S_E * H],   g_ehsL[S_E * H];
__device__ bf16 g_WqTH[H * H],     g_WqTL[H * H];
__device__ bf16 g_WkTH[512 * H],   g_WkTL[512 * H];
__device__ bf16 g_WvTH[512 * H],   g_WvTL[512 * H];
__device__ bf16 g_WoTH[H * H],     g_WoTL[H * H];
__device__ bf16 g_QH[S_Q * H],     g_QL[S_Q * H];
__device__ bf16 g_KH[S_E * 512],   g_KL[S_E * 512];
__device__ bf16 g_VTH[512 * S_E],  g_VTL[512 * S_E];
__device__ bf16 g_AOH[S_Q * H],    g_AOL[S_Q * H];

// ---------------- helpers ----------------
__device__ __forceinline__ unsigned smaddr(const void* p) {
    return (unsigned)__cvta_generic_to_shared(p);
}
__device__ __forceinline__ void ldm_x4(unsigned& r0, unsigned& r1, unsigned& r2, unsigned& r3,
                                       unsigned addr) {
    asm volatile("ldmatrix.sync.aligned.m8n8.x4.shared.b16 {%0,%1,%2,%3},[%4];\n"
                 : "=r"(r0), "=r"(r1), "=r"(r2), "=r"(r3) : "r"(addr));
}
__device__ __forceinline__ void ldm_x2(unsigned& r0, unsigned& r1, unsigned addr) {
    asm volatile("ldmatrix.sync.aligned.m8n8.x2.shared.b16 {%0,%1},[%2];\n"
                 : "=r"(r0), "=r"(r1) : "r"(addr));
}
__device__ __forceinline__ void mma16816(float* c, unsigned a0, unsigned a1, unsigned a2,
                                         unsigned a3, unsigned b0, unsigned b1) {
    asm volatile(
        "mma.sync.aligned.m16n8k16.row.col.f32.bf16.bf16.f32 "
        "{%0,%1,%2,%3},{%4,%5,%6,%7},{%8,%9},{%0,%1,%2,%3};\n"
        : "+f"(c[0]), "+f"(c[1]), "+f"(c[2]), "+f"(c[3])
        : "r"(a0), "r"(a1), "r"(a2), "r"(a3), "r"(b0), "r"(b1));
}
__device__ __forceinline__ void mma3(float* c, const unsigned* ah, const unsigned* al,
                                     unsigned bh0, unsigned bh1, unsigned bl0, unsigned bl1) {
    mma16816(c, ah[0], ah[1], ah[2], ah[3], bh0, bh1);
    mma16816(c, ah[0], ah[1], ah[2], ah[3], bl0, bl1);
    mma16816(c, al[0], al[1], al[2], al[3], bh0, bh1);
}
__device__ __forceinline__ void split2(float x, float y, unsigned& hi, unsigned& lo) {
    bf162 h; h.x = __float2bfloat16(x); h.y = __float2bfloat16(y);
    bf162 l; l.x = __float2bfloat16(x - __bfloat162float(h.x));
    l.y = __float2bfloat16(y - __bfloat162float(h.y));
    hi = *(unsigned*)&h; lo = *(unsigned*)&l;
}

// ---------------- prepass 1: split both activations ----------------
#define NQ4 (S_Q * H / 4)
#define NE4 (S_E * H / 4)
__global__ __launch_bounds__(256) void conv_split_all(
    const float* __restrict__ hs, const float* __restrict__ ehs,
    bf16* __restrict__ hsH, bf16* __restrict__ hsL,
    bf16* __restrict__ ehsH, bf16* __restrict__ ehsL)
{
    int i = blockIdx.x * 256 + threadIdx.x;
    const float* X; bf16 *Xh, *Xl;
    if (i < NQ4) { X = hs; Xh = hsH; Xl = hsL; }
    else { i -= NQ4; if (i >= NE4) return; X = ehs; Xh = ehsH; Xl = ehsL; }
    float4 v = *(const float4*)&X[(size_t)i * 4];
    unsigned h0, l0, h1, l1;
    split2(v.x, v.y, h0, l0);
    split2(v.z, v.w, h1, l1);
    float2 ho, lo;
    ((unsigned*)&ho)[0] = h0; ((unsigned*)&ho)[1] = h1;
    ((unsigned*)&lo)[0] = l0; ((unsigned*)&lo)[1] = l1;
    *(float2*)&Xh[(size_t)i * 4] = ho;
    *(float2*)&Xl[(size_t)i * 4] = lo;
}

// ---------------- prepass 2: transpose+split all weights ----------------
__global__ __launch_bounds__(256) void convT_all(
    const float* __restrict__ Wq, const float* __restrict__ Wk,
    const float* __restrict__ Wv, const float* __restrict__ Wo,
    bf16* __restrict__ qTh, bf16* __restrict__ qTl,
    bf16* __restrict__ kTh, bf16* __restrict__ kTl,
    bf16* __restrict__ vTh, bf16* __restrict__ vTl,
    bf16* __restrict__ oTh, bf16* __restrict__ oTl)
{
    const float* W; bf16 *Th, *Tl; int N;
    switch (blockIdx.z) {
        case 0: W = Wq; Th = qTh; Tl = qTl; N = 2048; break;
        case 1: W = Wk; Th = kTh; Tl = kTl; N = 512; break;
        case 2: W = Wv; Th = vTh; Tl = vTl; N = 512; break;
        default: W = Wo; Th = oTh; Tl = oTl; N = 2048; break;
    }
    const int n0 = blockIdx.x * 32;
    if (n0 >= N) return;
    const int k0 = blockIdx.y * 32;
    __shared__ float t[32][33];
    const int tx = threadIdx.x & 31;
    const int ty = threadIdx.x >> 5;
#pragma unroll
    for (int i = 0; i < 4; i++)
        t[ty + 8 * i][tx] = W[(size_t)(k0 + ty + 8 * i) * N + n0 + tx];
    __syncthreads();
#pragma unroll
    for (int i = 0; i < 4; i++) {
        int n = ty + 8 * i;
        float v = t[tx][n];
        bf16 h = __float2bfloat16(v);
        Th[(size_t)(n0 + n) * H + k0 + tx] = h;
        Tl[(size_t)(n0 + n) * H + k0 + tx] = __float2bfloat16(v - __bfloat162float(h));
    }
}

// ---------------- GEMM (mma.sync bf16x3), proven R4 version ----------------
__global__ __launch_bounds__(256) void gemm_x3(
    const bf16* __restrict__ Ahi, const bf16* __restrict__ Alo,
    const bf16* __restrict__ Bhi, const bf16* __restrict__ Blo,
    const float* __restrict__ bias, const float* __restrict__ nw,
    float* __restrict__ Cf, bf16* __restrict__ Chi, bf16* __restrict__ Clo,
    int M, int N, int K, int mode, int vt_stride)
{
    __shared__ unsigned sAhi[128 * 20], sAlo[128 * 20];
    __shared__ unsigned sBhi[128 * 20], sBlo[128 * 20];
    __shared__ float ssq[128];

    const int tid  = threadIdx.x;
    const int lane = tid & 31;
    const int warp = tid >> 5;
    const int wm   = warp >> 2;
    const int wn   = warp & 3;
    const int g    = lane >> 2;
    const int th   = lane & 3;
    const int m0   = blockIdx.y * 128;
    const int n0   = blockIdx.x * 128;

    float acc[4][4][4];
#pragma unroll
    for (int i = 0; i < 4; i++)
#pragma unroll
        for (int j = 0; j < 4; j++)
#pragma unroll
            for (int c = 0; c < 4; c++) acc[i][j][c] = 0.f;

    float4 pAh[2], pAl[2], pBh[2], pBl[2];
#pragma unroll
    for (int l = 0; l < 2; l++) {
        int gi = l * 256 + tid;
        int row = gi >> 2, seg = gi & 3;
        pAh[l] = *(const float4*)&Ahi[(size_t)(m0 + row) * K + seg * 8];
        pAl[l] = *(const float4*)&Alo[(size_t)(m0 + row) * K + seg * 8];
        pBh[l] = *(const float4*)&Bhi[(size_t)(n0 + row) * K + seg * 8];
        pBl[l] = *(const float4*)&Blo[(size_t)(n0 + row) * K + seg * 8];
    }

    const int nK = K / 32;
    for (int kt = 0; kt < nK; kt++) {
#pragma unroll
        for (int l = 0; l < 2; l++) {
            int gi = l * 256 + tid;
            int row = gi >> 2, seg = gi & 3;
            int o = row * 20 + seg * 4;
            *(float2*)&sAhi[o]     = make_float2(pAh[l].x, pAh[l].y);
            *(float2*)&sAhi[o + 2] = make_float2(pAh[l].z, pAh[l].w);
            *(float2*)&sAlo[o]     = make_float2(pAl[l].x, pAl[l].y);
            *(float2*)&sAlo[o + 2] = make_float2(pAl[l].z, pAl[l].w);
            *(float2*)&sBhi[o]     = make_float2(pBh[l].x, pBh[l].y);
            *(float2*)&sBhi[o + 2] = make_float2(pBh[l].z, pBh[l].w);
            *(float2*)&sBlo[o]     = make_float2(pBl[l].x, pBl[l].y);
            *(float2*)&sBlo[o + 2] = make_float2(pBl[l].z, pBl[l].w);
        }
        __syncthreads();
        if (kt + 1 < nK) {
            int kk = (kt + 1) * 32;
#pragma unroll
            for (int l = 0; l < 2; l++) {
                int gi = l * 256 + tid;
                int row = gi >> 2, seg = gi & 3;
                pAh[l] = *(const float4*)&Ahi[(size_t)(m0 + row) * K + kk + seg * 8];
                pAl[l] = *(const float4*)&Alo[(size_t)(m0 + row) * K + kk + seg * 8];
                pBh[l] = *(const float4*)&Bhi[(size_t)(n0 + row) * K + kk + seg * 8];
                pBl[l] = *(const float4*)&Blo[(size_t)(n0 + row) * K + kk + seg * 8];
            }
        }
#pragma unroll
        for (int ks = 0; ks < 2; ks++) {
            unsigned ahi[4][4], alo[4][4];
            const int rowl = wm * 64 + (lane & 15);
            const int colu = ks * 8 + (lane >> 4) * 4;
#pragma unroll
            for (int mt = 0; mt < 4; mt++) {
                ldm_x4(ahi[mt][0], ahi[mt][1], ahi[mt][2], ahi[mt][3],
                       smaddr(&sAhi[(rowl + mt * 16) * 20 + colu]));
                ldm_x4(alo[mt][0], alo[mt][1], alo[mt][2], alo[mt][3],
                       smaddr(&sAlo[(rowl + mt * 16) * 20 + colu]));
            }
            const int rowb = lane & 7;
            const int colb = ks * 8 + ((lane >> 3) & 1) * 4;
#pragma unroll
            for (int nt = 0; nt < 4; nt++) {
                unsigned bh0, bh1, bl0, bl1;
                ldm_x2(bh0, bh1, smaddr(&sBhi[(wn * 32 + nt * 8 + rowb) * 20 + colb]));
                ldm_x2(bl0, bl1, smaddr(&sBlo[(wn * 32 + nt * 8 + rowb) * 20 + colb]));
#pragma unroll
                for (int mt = 0; mt < 4; mt++)
                    mma3(acc[mt][nt], ahi[mt], alo[mt], bh0, bh1, bl0, bl1);
            }
        }
        __syncthreads();
    }

    if (bias) {
#pragma unroll
        for (int nt = 0; nt < 4; nt++) {
            int cc = n0 + wn * 32 + nt * 8 + th * 2;
            float b0 = bias[cc], b1 = bias[cc + 1];
#pragma unroll
            for (int mt = 0; mt < 4; mt++) {
                acc[mt][nt][0] += b0; acc[mt][nt][1] += b1;
                acc[mt][nt][2] += b0; acc[mt][nt][3] += b1;
            }
        }
    }

    if (mode == 0) {
#pragma unroll
        for (int mt = 0; mt < 4; mt++) {
            int r0 = m0 + wm * 64 + mt * 16 + g;
#pragma unroll
            for (int nt = 0; nt < 4; nt++) {
                int cc = n0 + wn * 32 + nt * 8 + th * 2;
                *(float2*)&Cf[(size_t)r0 * N + cc] = make_float2(acc[mt][nt][0], acc[mt][nt][1]);
                *(float2*)&Cf[(size_t)(r0 + 8) * N + cc] = make_float2(acc[mt][nt][2], acc[mt][nt][3]);
            }
        }
    } else if (mode == 1) {
        if (tid < 128) ssq[tid] = 0.f;
        __syncthreads();
#pragma unroll
        for (int mt = 0; mt < 4; mt++) {
            int rl = wm * 64 + mt * 16 + g;
            float p0 = 0.f, p1 = 0.f;
#pragma unroll
            for (int nt = 0; nt < 4; nt++) {
                p0 += acc[mt][nt][0] * acc[mt][nt][0] + acc[mt][nt][1] * acc[mt][nt][1];
                p1 += acc[mt][nt][2] * acc[mt][nt][2] + acc[mt][nt][3] * acc[mt][nt][3];
            }
            atomicAdd(&ssq[rl], p0);
            atomicAdd(&ssq[rl + 8], p1);
        }
        __syncthreads();
#pragma unroll
        for (int mt = 0; mt < 4; mt++) {
            int rl = wm * 64 + mt * 16 + g;
            float inv0 = rsqrtf(ssq[rl] * (1.0f / HD) + EPS);
            float inv1 = rsqrtf(ssq[rl + 8] * (1.0f / HD) + EPS);
#pragma unroll
            for (int nt = 0; nt < 4; nt++) {
                int col = wn * 32 + nt * 8 + th * 2;
                float w0 = nw[col], w1 = nw[col + 1];
                unsigned h, l;
                split2(acc[mt][nt][0] * inv0 * w0, acc[mt][nt][1] * inv0 * w1, h, l);
                *(unsigned*)&Chi[(size_t)(m0 + rl) * N + n0 + col] = h;
                *(unsigned*)&Clo[(size_t)(m0 + rl) * N + n0 + col] = l;
                split2(acc[mt][nt][2] * inv1 * w0, acc[mt][nt][3] * inv1 * w1, h, l);
                *(unsigned*)&Chi[(size_t)(m0 + rl + 8) * N + n0 + col] = h;
                *(unsigned*)&Clo[(size_t)(m0 + rl + 8) * N + n0 + col] = l;
            }
        }
    } else {
#pragma unroll
        for (int mt = 0; mt < 4; mt++) {
            int r0 = m0 + wm * 64 + mt * 16 + g;
#pragma unroll
            for (int nt = 0; nt < 4; nt++) {
                int cn = n0 + wn * 32 + nt * 8 + th * 2;
#pragma unroll
                for (int j = 0; j < 2; j++) {
                    float v0 = acc[mt][nt][j];
                    float v1 = acc[mt][nt][2 + j];
                    bf16 h0 = __float2bfloat16(v0);
                    bf16 h1 = __float2bfloat16(v1);
                    Chi[(size_t)(cn + j) * vt_stride + r0] = h0;
                    Chi[(size_t)(cn + j) * vt_stride + r0 + 8] = h1;
                    Clo[(size_t)(cn + j) * vt_stride + r0] =
                        __float2bfloat16(v0 - __bfloat162float(h0));
                    Clo[(size_t)(cn + j) * vt_stride + r0 + 8] =
                        __float2bfloat16(v1 - __bfloat162float(h1));
                }
            }
        }
    }
}

// ---------------- flash v3: 256 thr, 8 warps x 16 q-rows, kv-tile 64, Q in regs ----------------
#define FL2_SMEM_U32 (2 * (64 * 68) + 2 * (128 * 36))
#define FL2_SMEM_BYTES (FL2_SMEM_U32 * 4)

__global__ __launch_bounds__(256, 1) void flash_x3c(
    const bf16* __restrict__ Qhi, const bf16* __restrict__ Qlo,
    const bf16* __restrict__ Khi, const bf16* __restrict__ Klo,
    const bf16* __restrict__ VThi, const bf16* __restrict__ VTlo,
    const float* __restrict__ mask,
    bf16* __restrict__ AOhi, bf16* __restrict__ AOlo)
{
    extern __shared__ unsigned sm2[];
    unsigned* sKhi = sm2;                 // [64][68]
    unsigned* sKlo = sKhi + 64 * 68;
    unsigned* sVhi = sKlo + 64 * 68;      // [128][36] rows=hd, cols=e pairs
    unsigned* sVlo = sVhi + 128 * 36;

    const int h  = blockIdx.y;
    const int kh = h >> 2;
    const int q0 = blockIdx.x * 128;
    const int tid  = threadIdx.x;
    const int lane = tid & 31;
    const int w    = tid >> 5;            // warp = q sub-block (16 rows)
    const int g    = lane >> 2;
    const int th   = lane & 3;

    // ---- Q fragments in registers (A-frag layout: 2 consecutive bf16 per reg) ----
    unsigned qh[8][4], ql[8][4];
    {
        const size_t rq0 = (size_t)(q0 + w * 16 + g) * (NH * HD) + h * HD;
        const size_t rq8 = rq0 + (size_t)8 * (NH * HD);
#pragma unroll
        for (int ks = 0; ks < 8; ks++) {
            const int c = ks * 16 + th * 2;
            qh[ks][0] = *(const unsigned*)&Qhi[rq0 + c];
            qh[ks][1] = *(const unsigned*)&Qhi[rq8 + c];
            qh[ks][2] = *(const unsigned*)&Qhi[rq0 + c + 8];
            qh[ks][3] = *(const unsigned*)&Qhi[rq8 + c + 8];
            ql[ks][0] = *(const unsigned*)&Qlo[rq0 + c];
            ql[ks][1] = *(const unsigned*)&Qlo[rq8 + c];
            ql[ks][2] = *(const unsigned*)&Qlo[rq0 + c + 8];
            ql[ks][3] = *(const unsigned*)&Qlo[rq8 + c + 8];
        }
    }

    const float scale = 0.08838834764831845f;
    float o[16][4];
    float m0i = -INFINITY, m1i = -INFINITY, l0i = 0.f, l1i = 0.f;
#pragma unroll
    for (int nt = 0; nt < 16; nt++)
#pragma unroll
        for (int c = 0; c < 4; c++) o[nt][c] = 0.f;

    const int r0 = q0 + w * 16 + g;

    for (int e0 = 0; e0 < S_E; e0 += 64) {
        __syncthreads();
        // K tile: 64 rows x 128 bf16, hi+lo (4096 u32 each)
#pragma unroll
        for (int l = 0; l < 4; l++) {
            int gi = l * 256 + tid;
            int row = gi >> 4, c8 = gi & 15;
            float4 vh = *(const float4*)&Khi[(size_t)(e0 + row) * (NKV * HD) + kh * HD + c8 * 8];
            float4 vl = *(const float4*)&Klo[(size_t)(e0 + row) * (NKV * HD) + kh * HD + c8 * 8];
            *(float4*)&sKhi[row * 68 + c8 * 4] = vh;
            *(float4*)&sKlo[row * 68 + c8 * 4] = vl;
        }
        // V tile: 128 hd-rows x 64 e-cols, hi+lo (4096 u32 each)
#pragma unroll
        for (int l = 0; l < 4; l++) {
            int gi = l * 256 + tid;
            int vrow = gi >> 3, c4 = gi & 7;
            float4 wh = *(const float4*)&VThi[(size_t)(kh * HD + vrow) * S_E + e0 + c4 * 8];
            float4 wl = *(const float4*)&VTlo[(size_t)(kh * HD + vrow) * S_E + e0 + c4 * 8];
            *(float4*)&sVhi[vrow * 36 + c4 * 4] = wh;
            *(float4*)&sVlo[vrow * 36 + c4 * 4] = wl;
        }
        __syncthreads();

        // ---- S = Q K^T : s[8][4], 16 rows x 64 kv per warp ----
        float s[8][4];
#pragma unroll
        for (int nt = 0; nt < 8; nt++)
#pragma unroll
            for (int c = 0; c < 4; c++) s[nt][c] = 0.f;

#pragma unroll
        for (int ks = 0; ks < 8; ks++) {
            const int rowb = lane & 7;
            const int colb = ks * 8 + ((lane >> 3) & 1) * 4;
#pragma unroll
            for (int nt = 0; nt < 8; nt++) {
                unsigned bh0, bh1, bl0, bl1;
                ldm_x2(bh0, bh1, smaddr(&sKhi[(nt * 8 + rowb) * 68 + colb]));
                ldm_x2(bl0, bl1, smaddr(&sKlo[(nt * 8 + rowb) * 68 + colb]));
                mma3(s[nt], qh[ks], ql[ks], bh0, bh1, bl0, bl1);
            }
        }

        // ---- scale + mask + online softmax (rows r0, r0+8) ----
#pragma unroll
        for (int nt = 0; nt < 8; nt++) {
            const int cbm = e0 + nt * 8 + th * 2;
            float2 mk0 = *(const float2*)&mask[(size_t)r0 * S_E + cbm];
            float2 mk1 = *(const float2*)&mask[(size_t)(r0 + 8) * S_E + cbm];
            s[nt][0] = s[nt][0] * scale + mk0.x;
            s[nt][1] = s[nt][1] * scale + mk0.y;
            s[nt][2] = s[nt][2] * scale + mk1.x;
            s[nt][3] = s[nt][3] * scale + mk1.y;
        }
        float mx0 = -INFINITY, mx1 = -INFINITY;
#pragma unroll
        for (int nt = 0; nt < 8; nt++) {
            mx0 = fmaxf(mx0, fmaxf(s[nt][0], s[nt][1]));
            mx1 = fmaxf(mx1, fmaxf(s[nt][2], s[nt][3]));
        }
        mx0 = fmaxf(mx0, __shfl_xor_sync(0xffffffffu, mx0, 1));
        mx0 = fmaxf(mx0, __shfl_xor_sync(0xffffffffu, mx0, 2));
        mx1 = fmaxf(mx1, __shfl_xor_sync(0xffffffffu, mx1, 1));
        mx1 = fmaxf(mx1, __shfl_xor_sync(0xffffffffu, mx1, 2));
        float mn0 = fmaxf(m0i, mx0);
        float mn1 = fmaxf(m1i, mx1);
        float cr0 = __expf(m0i - mn0);
        float cr1 = __expf(m1i - mn1);
        m0i = mn0; m1i = mn1;
        float sm0 = 0.f, sm1 = 0.f;
#pragma unroll
        for (int nt = 0; nt < 8; nt++) {
            s[nt][0] = __expf(s[nt][0] - mn0);
            s[nt][1] = __expf(s[nt][1] - mn0);
            s[nt][2] = __expf(s[nt][2] - mn1);
            s[nt][3] = __expf(s[nt][3] - mn1);
            sm0 += s[nt][0] + s[nt][1];
            sm1 += s[nt][2] + s[nt][3];
        }
        sm0 += __shfl_xor_sync(0xffffffffu, sm0, 1);
        sm0 += __shfl_xor_sync(0xffffffffu, sm0, 2);
        sm1 += __shfl_xor_sync(0xffffffffu, sm1, 1);
        sm1 += __shfl_xor_sync(0xffffffffu, sm1, 2);
        l0i = l0i * cr0 + sm0;
        l1i = l1i * cr1 + sm1;
#pragma unroll
        for (int nt = 0; nt < 16; nt++) {
            o[nt][0] *= cr0;
            o[nt][1] *= cr0;
            o[nt][2] *= cr1;
            o[nt][3] *= cr1;
        }

        // ---- O += P V ----
#pragma unroll
        for (int ks2 = 0; ks2 < 4; ks2++) {
            unsigned phi[4], plo[4];
            const float* sa = s[2 * ks2];
            const float* sb = s[2 * ks2 + 1];
            split2(sa[0], sa[1], phi[0], plo[0]);
            split2(sa[2], sa[3], phi[1], plo[1]);
            split2(sb[0], sb[1], phi[2], plo[2]);
            split2(sb[2], sb[3], phi[3], plo[3]);
            const int rowv = lane & 7;
            const int colv = ks2 * 8 + ((lane >> 3) & 1) * 4;
#pragma unroll
            for (int nt2 = 0; nt2 < 16; nt2++) {
                unsigned vh0, vh1, vl0, vl1;
                ldm_x2(vh0, vh1, smaddr(&sVhi[(nt2 * 8 + rowv) * 36 + colv]));
                ldm_x2(vl0, vl1, smaddr(&sVlo[(nt2 * 8 + rowv) * 36 + colv]));
                mma3(o[nt2], phi, plo, vh0, vh1, vl0, vl1);
            }
        }
    }

    // ---- epilogue ----
    const float inv0 = 1.0f / l0i;
    const float inv1 = 1.0f / l1i;
#pragma unroll
    for (int nt2 = 0; nt2 < 16; nt2++) {
        const int cc = h * HD + nt2 * 8 + th * 2;
        unsigned hh, ll;
        split2(o[nt2][0] * inv0, o[nt2][1] * inv0, hh, ll);
        *(unsigned*)&AOhi[(size_t)r0 * (NH * HD) + cc] = hh;
        *(unsigned*)&AOlo[(size_t)r0 * (NH * HD) + cc] = ll;
        split2(o[nt2][2] * inv1, o[nt2][3] * inv1, hh, ll);
        *(unsigned*)&AOhi[(size_t)(r0 + 8) * (NH * HD) + cc] = hh;
        *(unsigned*)&AOlo[(size_t)(r0 + 8) * (NH * HD) + cc] = ll;
    }
}

// ---------------- launch ----------------
#define SYM(p, s) cudaGetSymbolAddress((void**)&p, s)

extern "C" void kernel_launch(void* const* d_in, const int* in_sizes, int n_in,
                              void* d_out, int out_size)
{
    const float* hs   = (const float*)d_in[0];
    const float* ehs  = (const float*)d_in[1];
    const float* mask = (const float*)d_in[2];
    const float* Wq   = (const float*)d_in[3];
    const float* bq   = (const float*)d_in[4];
    const float* Wk   = (const float*)d_in[5];
    const float* bk   = (const float*)d_in[6];
    const float* Wv   = (const float*)d_in[7];
    const float* bv   = (const float*)d_in[8];
    const float* Wo   = (const float*)d_in[9];
    const float* qn   = (const float*)d_in[10];
    const float* kn   = (const float*)d_in[11];
    float* out = (float*)d_out;

    bf16 *hsH, *hsL, *ehsH, *ehsL, *WqTH, *WqTL, *WkTH, *WkTL, *WvTH, *WvTL, *WoTH, *WoTL;
    bf16 *QH, *QL, *KH, *KL, *VTH, *VTL, *AOH, *AOL;
    SYM(hsH, g_hsH);  SYM(hsL, g_hsL);
    SYM(ehsH, g_ehsH); SYM(ehsL, g_ehsL);
    SYM(WqTH, g_WqTH); SYM(WqTL, g_WqTL);
    SYM(WkTH, g_WkTH); SYM(WkTL, g_WkTL);
    SYM(WvTH, g_WvTH); SYM(WvTL, g_WvTL);
    SYM(WoTH, g_WoTH); SYM(WoTL, g_WoTL);
    SYM(QH, g_QH); SYM(QL, g_QL);
    SYM(KH, g_KH); SYM(KL, g_KL);
    SYM(VTH, g_VTH); SYM(VTL, g_VTL);
    SYM(AOH, g_AOH); SYM(AOL, g_AOL);

    cudaFuncSetAttribute(flash_x3c, cudaFuncAttributeMaxDynamicSharedMemorySize, FL2_SMEM_BYTES);

    // 0: activations split
    conv_split_all<<<(NQ4 + NE4 + 255) / 256, 256>>>(hs, ehs, hsH, hsL, ehsH, ehsL);
    // 1: weights transpose+split
    convT_all<<<dim3(64, 64, 4), 256>>>(Wq, Wk, Wv, Wo, WqTH, WqTL, WkTH, WkTL,
                                        WvTH, WvTL, WoTH, WoTL);
    // 2-4: projections
    gemm_x3<<<dim3(16, 16), 256>>>(hsH, hsL, WqTH, WqTL, bq, qn,
                                   nullptr, QH, QL, S_Q, H, H, 1, 0);
    gemm_x3<<<dim3(4, 32), 256>>>(ehsH, ehsL, WkTH, WkTL, bk, kn,
                                  nullptr, KH, KL, S_E, 512, H, 1, 0);
    gemm_x3<<<dim3(4, 32), 256>>>(ehsH, ehsL, WvTH, WvTL, bv, nullptr,
                                  nullptr, VTH, VTL, S_E, 512, H, 2, S_E);
    // 5: attention (ncu -s 5 profiles this)
    flash_x3c<<<dim3(S_Q / 128, NH), 256, FL2_SMEM_BYTES>>>(QH, QL, KH, KL, VTH, VTL,
                                                            mask, AOH, AOL);
    // 6: output projection
    gemm_x3<<<dim3(16, 16), 256>>>(AOH, AOL, WoTH, WoTL, nullptr, nullptr,
                                   out, nullptr, nullptr, S_Q, H, NH * HD, 0, 0);
}